// round 6
// baseline (speedup 1.0000x reference)
#include <cuda_runtime.h>
#include <math.h>
#include <stdint.h>

#define B_ 16
#define N_ 1024
#define C_ 256

#define KC   16                 // k-chunk
#define STR  40                 // interleaved row stride in floats (32 data + 8 pad)
#define TILE (128 * STR)        // floats per operand tile (20 KB)

// scratch: V transposed to [B][C][N]
__device__ float g_Vt[(size_t)B_ * C_ * N_];

// ---------------------------------------------------------------------------
// mma.sync m16n8k8 tf32, row.col, fp32 accumulate
// ---------------------------------------------------------------------------
__device__ __forceinline__ void mma_tf32(float* d,
                                         float a0, float a1, float a2, float a3,
                                         float b0, float b1) {
    asm volatile(
        "mma.sync.aligned.m16n8k8.row.col.f32.tf32.tf32.f32 "
        "{%0,%1,%2,%3}, {%4,%5,%6,%7}, {%8,%9}, {%0,%1,%2,%3};"
        : "+f"(d[0]), "+f"(d[1]), "+f"(d[2]), "+f"(d[3])
        : "r"(__float_as_uint(a0)), "r"(__float_as_uint(a1)),
          "r"(__float_as_uint(a2)), "r"(__float_as_uint(a3)),
          "r"(__float_as_uint(b0)), "r"(__float_as_uint(b1)));
}

__device__ __forceinline__ void split_tf32(float x, float& h, float& l) {
    h = __uint_as_float(__float_as_uint(x) & 0xFFFFE000u);
    l = x - h;
}

// store split float4 (k=c4..c4+3) into interleaved tile: 2x float4 STS
__device__ __forceinline__ void store_i4(float* __restrict__ T, int row, int c4, float4 v) {
    float4 w0, w1;
    split_tf32(v.x, w0.x, w0.y);
    split_tf32(v.y, w0.z, w0.w);
    split_tf32(v.z, w1.x, w1.y);
    split_tf32(v.w, w1.z, w1.w);
    float* p = &T[row * STR + 2 * c4];
    *reinterpret_cast<float4*>(p)     = w0;
    *reinterpret_cast<float4*>(p + 4) = w1;
}

// ---------------------------------------------------------------------------
// one k-chunk (KC=16) of a 128x128 tile on 8 warps (2x4), 3xTF32
// A, B: interleaved (hi,lo) tiles, row stride STR
// ---------------------------------------------------------------------------
__device__ __forceinline__ void compute_chunk(
    const float* __restrict__ A, const float* __restrict__ B,
    float acc[4][4][4], int wm, int wn, int g, int cq)
{
#pragma unroll
    for (int s = 0; s < KC; s += 8) {
        const int co = 2 * s + 2 * cq;
        float2 a0[4], a1[4], a2[4], a3[4];
#pragma unroll
        for (int i = 0; i < 4; i++) {
            int r0 = (wm * 64 + i * 16 + g) * STR + co;
            int r1 = r0 + 8 * STR;
            a0[i] = *reinterpret_cast<const float2*>(&A[r0]);      // (hi,lo) k=s+cq
            a1[i] = *reinterpret_cast<const float2*>(&A[r1]);
            a2[i] = *reinterpret_cast<const float2*>(&A[r0 + 8]);  // k=s+cq+4
            a3[i] = *reinterpret_cast<const float2*>(&A[r1 + 8]);
        }
#pragma unroll
        for (int j = 0; j < 4; j++) {
            int rb = (wn * 32 + j * 8 + g) * STR + co;
            float2 b0 = *reinterpret_cast<const float2*>(&B[rb]);
            float2 b1 = *reinterpret_cast<const float2*>(&B[rb + 8]);
#pragma unroll
            for (int i = 0; i < 4; i++) {
                mma_tf32(acc[i][j], a0[i].x, a1[i].x, a2[i].x, a3[i].x, b0.x, b1.x); // hi*hi
                mma_tf32(acc[i][j], a0[i].y, a1[i].y, a2[i].y, a3[i].y, b0.x, b1.x); // lo*hi
                mma_tf32(acc[i][j], a0[i].x, a1[i].x, a2[i].x, a3[i].x, b0.y, b1.y); // hi*lo
            }
        }
    }
}

// ---------------------------------------------------------------------------
// Kernel 0: transpose V -> g_Vt  [B][N][C] -> [B][C][N]
// ---------------------------------------------------------------------------
__global__ __launch_bounds__(256) void transpose_v_kernel(const float* __restrict__ V)
{
    __shared__ float t[32][33];
    const int b  = blockIdx.z;
    const int n0 = blockIdx.y * 32;
    const int c0 = blockIdx.x * 32;
    const float* Vb = V + (size_t)b * N_ * C_;
    float* Tb = g_Vt + (size_t)b * C_ * N_;
    const int x = threadIdx.x, y = threadIdx.y;
#pragma unroll
    for (int dy = 0; dy < 32; dy += 8)
        t[y + dy][x] = Vb[(size_t)(n0 + y + dy) * C_ + c0 + x];
    __syncthreads();
#pragma unroll
    for (int dy = 0; dy < 32; dy += 8)
        Tb[(size_t)(c0 + y + dy) * N_ + n0 + x] = t[x][y + dy];
}

// ---------------------------------------------------------------------------
// Kernel 1: attn = masked((Q K^T + dis) * 0.0625). Double-buffered.
// ---------------------------------------------------------------------------
__global__ __launch_bounds__(256, 2) void qk_scores_kernel(
    const float* __restrict__ Q,
    const float* __restrict__ K,
    const float* __restrict__ dis,
    const int*   __restrict__ mask,
    float* __restrict__ attn)
{
    extern __shared__ float smem[];   // [2][A TILE, B TILE]

    const int b     = blockIdx.z;
    const int qBase = blockIdx.y * 128;
    const int kBase = blockIdx.x * 128;

    const float* Qb = Q + (size_t)b * N_ * C_;
    const float* Kb = K + (size_t)b * N_ * C_;

    const int tid  = threadIdx.x;
    const int lane = tid & 31;
    const int w    = tid >> 5;
    const int wm   = w >> 2;
    const int wn   = w & 3;
    const int g    = lane >> 2;
    const int cq   = lane & 3;

    const int lrow0 = tid >> 2;            // 0..63
    const int lrow1 = lrow0 + 64;          // 64..127
    const int lc4   = (tid & 3) * 4;

    float acc[4][4][4];
#pragma unroll
    for (int i = 0; i < 4; i++)
#pragma unroll
        for (int j = 0; j < 4; j++)
#pragma unroll
            for (int r = 0; r < 4; r++) acc[i][j][r] = 0.0f;

    float4 vq0, vq1, vk0, vk1;
    auto load_g = [&](int c0) {
        vq0 = *reinterpret_cast<const float4*>(&Qb[(size_t)(qBase + lrow0) * C_ + c0 + lc4]);
        vq1 = *reinterpret_cast<const float4*>(&Qb[(size_t)(qBase + lrow1) * C_ + c0 + lc4]);
        vk0 = *reinterpret_cast<const float4*>(&Kb[(size_t)(kBase + lrow0) * C_ + c0 + lc4]);
        vk1 = *reinterpret_cast<const float4*>(&Kb[(size_t)(kBase + lrow1) * C_ + c0 + lc4]);
    };
    auto store_s = [&](float* buf) {
        store_i4(buf,        lrow0, lc4, vq0);
        store_i4(buf,        lrow1, lc4, vq1);
        store_i4(buf + TILE, lrow0, lc4, vk0);
        store_i4(buf + TILE, lrow1, lc4, vk1);
    };

    load_g(0);
    store_s(smem);
    __syncthreads();

    int buf = 0;
    for (int c0 = 0; c0 < C_; c0 += KC, buf ^= 1) {
        const bool more = (c0 + KC) < C_;
        if (more) load_g(c0 + KC);
        const float* base = smem + buf * 2 * TILE;
        compute_chunk(base, base + TILE, acc, wm, wn, g, cq);
        if (more) store_s(smem + (buf ^ 1) * 2 * TILE);
        __syncthreads();
    }

    // epilogue: add dis, scale, mask -> attn
#pragma unroll
    for (int i = 0; i < 4; i++) {
        int r0 = qBase + wm * 64 + i * 16 + g;
        int r1 = r0 + 8;
#pragma unroll
        for (int j = 0; j < 4; j++) {
            int col = kBase + wn * 32 + j * 8 + 2 * cq;
            size_t i0 = ((size_t)b * N_ + r0) * N_ + col;
            size_t i1 = ((size_t)b * N_ + r1) * N_ + col;
            float2 d0 = *reinterpret_cast<const float2*>(&dis[i0]);
            float2 d1 = *reinterpret_cast<const float2*>(&dis[i1]);
            int2   m0 = *reinterpret_cast<const int2*>(&mask[i0]);
            int2   m1 = *reinterpret_cast<const int2*>(&mask[i1]);
            float2 o0, o1;
            o0.x = m0.x ? -INFINITY : (acc[i][j][0] + d0.x) * 0.0625f;
            o0.y = m0.y ? -INFINITY : (acc[i][j][1] + d0.y) * 0.0625f;
            o1.x = m1.x ? -INFINITY : (acc[i][j][2] + d1.x) * 0.0625f;
            o1.y = m1.y ? -INFINITY : (acc[i][j][3] + d1.y) * 0.0625f;
            *reinterpret_cast<float2*>(&attn[i0]) = o0;
            *reinterpret_cast<float2*>(&attn[i1]) = o1;
        }
    }
}

// ---------------------------------------------------------------------------
// Kernel 2: row softmax, shuffle-based, float4 I/O. One block per row.
// ---------------------------------------------------------------------------
__global__ __launch_bounds__(256) void softmax_kernel(float* __restrict__ attn)
{
    __shared__ float s1[8], s2[8];
    const size_t base = (size_t)blockIdx.x * N_;
    const int t = threadIdx.x;
    const int w = t >> 5, lane = t & 31;

    float4 v = *reinterpret_cast<const float4*>(&attn[base + t * 4]);

    float m = fmaxf(fmaxf(v.x, v.y), fmaxf(v.z, v.w));
#pragma unroll
    for (int o = 16; o; o >>= 1) m = fmaxf(m, __shfl_xor_sync(0xffffffffu, m, o));
    if (lane == 0) s1[w] = m;
    __syncthreads();
    float M = s1[0];
#pragma unroll
    for (int i = 1; i < 8; i++) M = fmaxf(M, s1[i]);

    float4 p;
    p.x = __expf(v.x - M); p.y = __expf(v.y - M);
    p.z = __expf(v.z - M); p.w = __expf(v.w - M);
    float s = (p.x + p.y) + (p.z + p.w);
#pragma unroll
    for (int o = 16; o; o >>= 1) s += __shfl_xor_sync(0xffffffffu, s, o);
    if (lane == 0) s2[w] = s;
    __syncthreads();
    float S = s2[0];
#pragma unroll
    for (int i = 1; i < 8; i++) S += s2[i];
    float inv = 1.0f / S;

    p.x *= inv; p.y *= inv; p.z *= inv; p.w *= inv;
    *reinterpret_cast<float4*>(&attn[base + t * 4]) = p;
}

// ---------------------------------------------------------------------------
// Kernel 3: p_val = p_attn @ V (via g_Vt). Same structure as qk.
// ---------------------------------------------------------------------------
__global__ __launch_bounds__(256, 2) void pv_kernel(
    const float* __restrict__ P,
    float* __restrict__ out)
{
    extern __shared__ float smem[];

    const int b     = blockIdx.z;
    const int qBase = blockIdx.y * 128;
    const int nBase = blockIdx.x * 128;    // channel-tile base (C)

    const float* Pb = P + (size_t)b * N_ * N_;
    const float* Vt = g_Vt + (size_t)b * C_ * N_;

    const int tid  = threadIdx.x;
    const int lane = tid & 31;
    const int w    = tid >> 5;
    const int wm   = w >> 2;
    const int wn   = w & 3;
    const int g    = lane >> 2;
    const int cq   = lane & 3;

    const int lrow0 = tid >> 2;
    const int lrow1 = lrow0 + 64;
    const int lc4   = (tid & 3) * 4;

    float acc[4][4][4];
#pragma unroll
    for (int i = 0; i < 4; i++)
#pragma unroll
        for (int j = 0; j < 4; j++)
#pragma unroll
            for (int r = 0; r < 4; r++) acc[i][j][r] = 0.0f;

    float4 vp0, vp1, vv0, vv1;
    auto load_g = [&](int k0) {
        vp0 = *reinterpret_cast<const float4*>(&Pb[(size_t)(qBase + lrow0) * N_ + k0 + lc4]);
        vp1 = *reinterpret_cast<const float4*>(&Pb[(size_t)(qBase + lrow1) * N_ + k0 + lc4]);
        vv0 = *reinterpret_cast<const float4*>(&Vt[(size_t)(nBase + lrow0) * N_ + k0 + lc4]);
        vv1 = *reinterpret_cast<const float4*>(&Vt[(size_t)(nBase + lrow1) * N_ + k0 + lc4]);
    };
    auto store_s = [&](float* buf) {
        store_i4(buf,        lrow0, lc4, vp0);
        store_i4(buf,        lrow1, lc4, vp1);
        store_i4(buf + TILE, lrow0, lc4, vv0);
        store_i4(buf + TILE, lrow1, lc4, vv1);
    };

    load_g(0);
    store_s(smem);
    __syncthreads();

    int buf = 0;
    for (int k0 = 0; k0 < N_; k0 += KC, buf ^= 1) {
        const bool more = (k0 + KC) < N_;
        if (more) load_g(k0 + KC);
        const float* base = smem + buf * 2 * TILE;
        compute_chunk(base, base + TILE, acc, wm, wn, g, cq);
        if (more) store_s(smem + (buf ^ 1) * 2 * TILE);
        __syncthreads();
    }

#pragma unroll
    for (int i = 0; i < 4; i++) {
        int r0 = qBase + wm * 64 + i * 16 + g;
        int r1 = r0 + 8;
#pragma unroll
        for (int j = 0; j < 4; j++) {
            int col = nBase + wn * 32 + j * 8 + 2 * cq;
            size_t i0 = ((size_t)b * N_ + r0) * C_ + col;
            size_t i1 = ((size_t)b * N_ + r1) * C_ + col;
            *reinterpret_cast<float2*>(&out[i0]) = make_float2(acc[i][j][0], acc[i][j][1]);
            *reinterpret_cast<float2*>(&out[i1]) = make_float2(acc[i][j][2], acc[i][j][3]);
        }
    }
}

// ---------------------------------------------------------------------------
// Launch
// ---------------------------------------------------------------------------
extern "C" void kernel_launch(void* const* d_in, const int* in_sizes, int n_in,
                              void* d_out, int out_size)
{
    const float* Q    = (const float*)d_in[0];
    const float* K    = (const float*)d_in[1];
    const float* V    = (const float*)d_in[2];
    const int*   mask = (const int*)d_in[3];
    const float* dis  = (const float*)d_in[4];

    float* out    = (float*)d_out;
    float* p_val  = out;                          // [B, N, C]
    float* p_attn = out + (size_t)B_ * N_ * C_;   // [B, N, N]

    const int smemBytes = 2 * 2 * TILE * sizeof(float);   // 81920
    static bool attrSet = false;
    if (!attrSet) {
        cudaFuncSetAttribute(qk_scores_kernel,
                             cudaFuncAttributeMaxDynamicSharedMemorySize, smemBytes);
        cudaFuncSetAttribute(pv_kernel,
                             cudaFuncAttributeMaxDynamicSharedMemorySize, smemBytes);
        attrSet = true;
    }

    transpose_v_kernel<<<dim3(C_ / 32, N_ / 32, B_), dim3(32, 8)>>>(V);
    qk_scores_kernel<<<dim3(N_ / 128, N_ / 128, B_), 256, smemBytes>>>(Q, K, dis, mask, p_attn);
    softmax_kernel<<<B_ * N_, 256>>>(p_attn);
    pv_kernel<<<dim3(C_ / 128, N_ / 128, B_), 256, smemBytes>>>(p_attn, p_val);
}

// round 8
// speedup vs baseline: 1.3387x; 1.3387x over previous
#include <cuda_runtime.h>
#include <math.h>
#include <stdint.h>

#define B_ 16
#define N_ 1024
#define C_ 256

#define KC   32                 // k-chunk (floats)
#define STR  36                 // smem row stride: 36 mod 32 = 4 -> rows spread banks
#define TILE (128 * STR)        // floats per (sub)tile
#define DYN_BYTES (4 * TILE * 4)  // Ah, Al, Bh, Bl = 73728 B

// V transposed to [B][C][N]
static __device__ float g_Vt[(size_t)B_ * C_ * N_];

// ---------------------------------------------------------------------------
// mma.sync m16n8k8 tf32, row.col, fp32 accumulate
// ---------------------------------------------------------------------------
__device__ __forceinline__ void mma_tf32(float* d,
                                         float a0, float a1, float a2, float a3,
                                         float b0, float b1) {
    asm volatile(
        "mma.sync.aligned.m16n8k8.row.col.f32.tf32.tf32.f32 "
        "{%0,%1,%2,%3}, {%4,%5,%6,%7}, {%8,%9}, {%0,%1,%2,%3};"
        : "+f"(d[0]), "+f"(d[1]), "+f"(d[2]), "+f"(d[3])
        : "r"(__float_as_uint(a0)), "r"(__float_as_uint(a1)),
          "r"(__float_as_uint(a2)), "r"(__float_as_uint(a3)),
          "r"(__float_as_uint(b0)), "r"(__float_as_uint(b1)));
}

__device__ __forceinline__ void split4(float4 v, float4& h, float4& l) {
    h.x = __uint_as_float(__float_as_uint(v.x) & 0xFFFFE000u); l.x = v.x - h.x;
    h.y = __uint_as_float(__float_as_uint(v.y) & 0xFFFFE000u); l.y = v.y - h.y;
    h.z = __uint_as_float(__float_as_uint(v.z) & 0xFFFFE000u); l.z = v.z - h.z;
    h.w = __uint_as_float(__float_as_uint(v.w) & 0xFFFFE000u); l.w = v.w - h.w;
}

// ---------------------------------------------------------------------------
// one k-chunk (KC=32): load gmem -> split -> smem; then 4 s-steps of mma
// 8 warps (2x4), warp tile 64x32, 4x4 m16n8 tiles, 3xTF32
// ---------------------------------------------------------------------------
__device__ __forceinline__ void load_tiles(
    const float* __restrict__ Ag, const float* __restrict__ Bg,
    int lda, int ldb, int aBase, int bBase, int k0,
    float* __restrict__ Ah, float* __restrict__ Al,
    float* __restrict__ Bh, float* __restrict__ Bl, int tid)
{
#pragma unroll
    for (int e = 0; e < 4; e++) {
        int lin = tid + e * 256;
        int row = lin >> 3;            // 0..127
        int c4  = (lin & 7) * 4;       // 0..28
        float4 va = *reinterpret_cast<const float4*>(
            &Ag[(size_t)(aBase + row) * lda + k0 + c4]);
        float4 vb = *reinterpret_cast<const float4*>(
            &Bg[(size_t)(bBase + row) * ldb + k0 + c4]);
        float4 h, l;
        int sidx = row * STR + c4;
        split4(va, h, l);
        *reinterpret_cast<float4*>(&Ah[sidx]) = h;
        *reinterpret_cast<float4*>(&Al[sidx]) = l;
        split4(vb, h, l);
        *reinterpret_cast<float4*>(&Bh[sidx]) = h;
        *reinterpret_cast<float4*>(&Bl[sidx]) = l;
    }
}

__device__ __forceinline__ void compute_chunk(
    const float* __restrict__ Ah, const float* __restrict__ Al,
    const float* __restrict__ Bh, const float* __restrict__ Bl,
    float acc[4][4][4], int wm, int wn, int g, int cq)
{
#pragma unroll
    for (int s = 0; s < KC; s += 8) {
        uint32_t co = s + cq;
        float ah[4][4], al[4][4];
#pragma unroll
        for (int i = 0; i < 4; i++) {
            int idx = (wm * 64 + i * 16 + g) * STR + co;
            ah[i][0] = Ah[idx];
            ah[i][1] = Ah[idx + 8 * STR];
            ah[i][2] = Ah[idx + 4];
            ah[i][3] = Ah[idx + 8 * STR + 4];
            al[i][0] = Al[idx];
            al[i][1] = Al[idx + 8 * STR];
            al[i][2] = Al[idx + 4];
            al[i][3] = Al[idx + 8 * STR + 4];
        }
#pragma unroll
        for (int j = 0; j < 4; j++) {
            int bidx = (wn * 32 + j * 8 + g) * STR + co;
            float bh0 = Bh[bidx], bh1 = Bh[bidx + 4];
            float bl0 = Bl[bidx], bl1 = Bl[bidx + 4];
#pragma unroll
            for (int i = 0; i < 4; i++) {
                mma_tf32(acc[i][j], ah[i][0], ah[i][1], ah[i][2], ah[i][3], bh0, bh1);
                mma_tf32(acc[i][j], al[i][0], al[i][1], al[i][2], al[i][3], bh0, bh1);
                mma_tf32(acc[i][j], ah[i][0], ah[i][1], ah[i][2], ah[i][3], bl0, bl1);
            }
        }
    }
}

// ---------------------------------------------------------------------------
// Kernel 0: transpose V -> g_Vt  [B][N][C] -> [B][C][N]
// ---------------------------------------------------------------------------
__global__ __launch_bounds__(256) void transpose_v_kernel(const float* __restrict__ V)
{
    __shared__ float t[32][33];
    const int b  = blockIdx.z;
    const int n0 = blockIdx.y * 32;
    const int c0 = blockIdx.x * 32;
    const float* Vb = V + (size_t)b * N_ * C_;
    float* Tb = g_Vt + (size_t)b * C_ * N_;
    const int x = threadIdx.x, y = threadIdx.y;
#pragma unroll
    for (int dy = 0; dy < 32; dy += 8)
        t[y + dy][x] = Vb[(size_t)(n0 + y + dy) * C_ + c0 + x];
    __syncthreads();
#pragma unroll
    for (int dy = 0; dy < 32; dy += 8)
        Tb[(size_t)(c0 + y + dy) * N_ + n0 + x] = t[x][y + dy];
}

// ---------------------------------------------------------------------------
// Kernel 1: attn = masked((Q K^T + dis) * 0.0625)
// ---------------------------------------------------------------------------
__global__ __launch_bounds__(256, 2) void qk_scores_kernel(
    const float* __restrict__ Q,
    const float* __restrict__ K,
    const float* __restrict__ dis,
    const int*   __restrict__ mask,
    float* __restrict__ attn)
{
    extern __shared__ float smem[];
    float* Ah = smem;
    float* Al = smem + TILE;
    float* Bh = smem + 2 * TILE;
    float* Bl = smem + 3 * TILE;

    const int b     = blockIdx.z;
    const int qBase = blockIdx.y * 128;
    const int kBase = blockIdx.x * 128;

    const float* Qb = Q + (size_t)b * N_ * C_;
    const float* Kb = K + (size_t)b * N_ * C_;

    const int tid  = threadIdx.x;
    const int lane = tid & 31;
    const int w    = tid >> 5;
    const int wm   = w >> 2;
    const int wn   = w & 3;
    const int g    = lane >> 2;
    const int cq   = lane & 3;

    float acc[4][4][4];
#pragma unroll
    for (int i = 0; i < 4; i++)
#pragma unroll
        for (int j = 0; j < 4; j++)
#pragma unroll
            for (int r = 0; r < 4; r++) acc[i][j][r] = 0.0f;

    for (int c0 = 0; c0 < C_; c0 += KC) {
        load_tiles(Qb, Kb, C_, C_, qBase, kBase, c0, Ah, Al, Bh, Bl, tid);
        __syncthreads();
        compute_chunk(Ah, Al, Bh, Bl, acc, wm, wn, g, cq);
        __syncthreads();
    }

    // epilogue: add dis, scale, mask
#pragma unroll
    for (int i = 0; i < 4; i++) {
        int r0 = qBase + wm * 64 + i * 16 + g;
        int r1 = r0 + 8;
#pragma unroll
        for (int j = 0; j < 4; j++) {
            int col = kBase + wn * 32 + j * 8 + 2 * cq;
            size_t i0 = ((size_t)b * N_ + r0) * N_ + col;
            size_t i1 = ((size_t)b * N_ + r1) * N_ + col;
            float2 d0 = *reinterpret_cast<const float2*>(&dis[i0]);
            float2 d1 = *reinterpret_cast<const float2*>(&dis[i1]);
            int2   m0 = *reinterpret_cast<const int2*>(&mask[i0]);
            int2   m1 = *reinterpret_cast<const int2*>(&mask[i1]);
            float2 o0, o1;
            o0.x = m0.x ? -INFINITY : (acc[i][j][0] + d0.x) * 0.0625f;
            o0.y = m0.y ? -INFINITY : (acc[i][j][1] + d0.y) * 0.0625f;
            o1.x = m1.x ? -INFINITY : (acc[i][j][2] + d1.x) * 0.0625f;
            o1.y = m1.y ? -INFINITY : (acc[i][j][3] + d1.y) * 0.0625f;
            *reinterpret_cast<float2*>(&attn[i0]) = o0;
            *reinterpret_cast<float2*>(&attn[i1]) = o1;
        }
    }
}

// ---------------------------------------------------------------------------
// Kernel 2: row softmax (rows of 1024), shuffle-based, float4 I/O
// ---------------------------------------------------------------------------
__global__ __launch_bounds__(256) void softmax_kernel(float* __restrict__ attn)
{
    __shared__ float s1[8], s2[8];
    const size_t base = (size_t)blockIdx.x * N_;
    const int t = threadIdx.x;
    const int w = t >> 5, lane = t & 31;

    float4 v = *reinterpret_cast<const float4*>(&attn[base + t * 4]);

    float m = fmaxf(fmaxf(v.x, v.y), fmaxf(v.z, v.w));
#pragma unroll
    for (int o = 16; o; o >>= 1) m = fmaxf(m, __shfl_xor_sync(0xffffffffu, m, o));
    if (lane == 0) s1[w] = m;
    __syncthreads();
    float M = s1[0];
#pragma unroll
    for (int i = 1; i < 8; i++) M = fmaxf(M, s1[i]);

    float4 p;
    p.x = __expf(v.x - M); p.y = __expf(v.y - M);
    p.z = __expf(v.z - M); p.w = __expf(v.w - M);
    float s = (p.x + p.y) + (p.z + p.w);
#pragma unroll
    for (int o = 16; o; o >>= 1) s += __shfl_xor_sync(0xffffffffu, s, o);
    if (lane == 0) s2[w] = s;
    __syncthreads();
    float S = s2[0];
#pragma unroll
    for (int i = 1; i < 8; i++) S += s2[i];
    float inv = 1.0f / S;

    p.x *= inv; p.y *= inv; p.z *= inv; p.w *= inv;
    *reinterpret_cast<float4*>(&attn[base + t * 4]) = p;
}

// ---------------------------------------------------------------------------
// Kernel 3: p_val = p_attn @ V (B from g_Vt, K-major) — same structure as qk
// ---------------------------------------------------------------------------
__global__ __launch_bounds__(256, 2) void pv_kernel(
    const float* __restrict__ P,
    float* __restrict__ out)
{
    extern __shared__ float smem[];
    float* Ah = smem;
    float* Al = smem + TILE;
    float* Bh = smem + 2 * TILE;
    float* Bl = smem + 3 * TILE;

    const int b     = blockIdx.z;
    const int qBase = blockIdx.y * 128;
    const int nBase = blockIdx.x * 128;

    const float* Pb = P + (size_t)b * N_ * N_;
    const float* Vt = g_Vt + (size_t)b * C_ * N_;

    const int tid  = threadIdx.x;
    const int lane = tid & 31;
    const int w    = tid >> 5;
    const int wm   = w >> 2;
    const int wn   = w & 3;
    const int g    = lane >> 2;
    const int cq   = lane & 3;

    float acc[4][4][4];
#pragma unroll
    for (int i = 0; i < 4; i++)
#pragma unroll
        for (int j = 0; j < 4; j++)
#pragma unroll
            for (int r = 0; r < 4; r++) acc[i][j][r] = 0.0f;

    for (int k0 = 0; k0 < N_; k0 += KC) {
        load_tiles(Pb, Vt, N_, N_, qBase, nBase, k0, Ah, Al, Bh, Bl, tid);
        __syncthreads();
        compute_chunk(Ah, Al, Bh, Bl, acc, wm, wn, g, cq);
        __syncthreads();
    }

#pragma unroll
    for (int i = 0; i < 4; i++) {
        int r0 = qBase + wm * 64 + i * 16 + g;
        int r1 = r0 + 8;
#pragma unroll
        for (int j = 0; j < 4; j++) {
            int col = nBase + wn * 32 + j * 8 + 2 * cq;
            size_t i0 = ((size_t)b * N_ + r0) * C_ + col;
            size_t i1 = ((size_t)b * N_ + r1) * C_ + col;
            *reinterpret_cast<float2*>(&out[i0]) = make_float2(acc[i][j][0], acc[i][j][1]);
            *reinterpret_cast<float2*>(&out[i1]) = make_float2(acc[i][j][2], acc[i][j][3]);
        }
    }
}

// ---------------------------------------------------------------------------
// Launch
// ---------------------------------------------------------------------------
extern "C" void kernel_launch(void* const* d_in, const int* in_sizes, int n_in,
                              void* d_out, int out_size)
{
    const float* Q    = (const float*)d_in[0];
    const float* K    = (const float*)d_in[1];
    const float* V    = (const float*)d_in[2];
    const int*   mask = (const int*)d_in[3];
    const float* dis  = (const float*)d_in[4];

    float* out    = (float*)d_out;
    float* p_val  = out;                          // [B, N, C]
    float* p_attn = out + (size_t)B_ * N_ * C_;   // [B, N, N]

    cudaFuncSetAttribute(qk_scores_kernel,
                         cudaFuncAttributeMaxDynamicSharedMemorySize, DYN_BYTES);
    cudaFuncSetAttribute(pv_kernel,
                         cudaFuncAttributeMaxDynamicSharedMemorySize, DYN_BYTES);

    transpose_v_kernel<<<dim3(C_ / 32, N_ / 32, B_), dim3(32, 8)>>>(V);
    qk_scores_kernel<<<dim3(N_ / 128, N_ / 128, B_), 256, DYN_BYTES>>>(Q, K, dis, mask, p_attn);
    softmax_kernel<<<B_ * N_, 256>>>(p_attn);
    pv_kernel<<<dim3(C_ / 128, N_ / 128, B_), 256, DYN_BYTES>>>(p_attn, p_val);
}

// round 9
// speedup vs baseline: 1.5135x; 1.1305x over previous
#include <cuda_runtime.h>
#include <math.h>
#include <stdint.h>

#define B_ 16
#define N_ 1024
#define C_ 256

#define KC   32                 // k-chunk (floats)
#define STR  36                 // smem row stride: 36 mod 32 = 4 -> rows spread banks
#define TILE (128 * STR)        // floats per raw tile (18 KB)

// V transposed to [B][C][N]
static __device__ float g_Vt[(size_t)B_ * C_ * N_];

// ---------------------------------------------------------------------------
// mma.sync m16n8k8 tf32, row.col, fp32 accumulate
// ---------------------------------------------------------------------------
__device__ __forceinline__ void mma_tf32(float* d,
                                         float a0, float a1, float a2, float a3,
                                         float b0, float b1) {
    asm volatile(
        "mma.sync.aligned.m16n8k8.row.col.f32.tf32.tf32.f32 "
        "{%0,%1,%2,%3}, {%4,%5,%6,%7}, {%8,%9}, {%0,%1,%2,%3};"
        : "+f"(d[0]), "+f"(d[1]), "+f"(d[2]), "+f"(d[3])
        : "r"(__float_as_uint(a0)), "r"(__float_as_uint(a1)),
          "r"(__float_as_uint(a2)), "r"(__float_as_uint(a3)),
          "r"(__float_as_uint(b0)), "r"(__float_as_uint(b1)));
}

__device__ __forceinline__ float hi_part(float x) {
    return __uint_as_float(__float_as_uint(x) & 0xFFFFE000u);
}

// ---------------------------------------------------------------------------
// cooperative raw tile load: 128 x KC floats each for A and B
// ---------------------------------------------------------------------------
__device__ __forceinline__ void load_tiles(
    const float* __restrict__ Ag, const float* __restrict__ Bg,
    int lda, int ldb, int aBase, int bBase, int k0,
    float* __restrict__ As, float* __restrict__ Bs, int tid)
{
#pragma unroll
    for (int e = 0; e < 4; e++) {
        int lin = tid + e * 256;
        int row = lin >> 3;            // 0..127
        int c4  = (lin & 7) * 4;       // 0..28
        float4 va = *reinterpret_cast<const float4*>(
            &Ag[(size_t)(aBase + row) * lda + k0 + c4]);
        float4 vb = *reinterpret_cast<const float4*>(
            &Bg[(size_t)(bBase + row) * ldb + k0 + c4]);
        int sidx = row * STR + c4;
        *reinterpret_cast<float4*>(&As[sidx]) = va;
        *reinterpret_cast<float4*>(&Bs[sidx]) = vb;
    }
}

// ---------------------------------------------------------------------------
// one k-chunk (KC=32): raw tiles -> split in registers -> 3xTF32 mma
// 8 warps (2x4), warp tile 64x32, 4x4 m16n8 tiles
// ---------------------------------------------------------------------------
__device__ __forceinline__ void compute_chunk(
    const float* __restrict__ As, const float* __restrict__ Bs,
    float acc[4][4][4], int wm, int wn, int g, int cq)
{
#pragma unroll
    for (int s = 0; s < KC; s += 8) {
        const int co = s + cq;
        float ah[4][4], al[4][4];
#pragma unroll
        for (int i = 0; i < 4; i++) {
            int idx = (wm * 64 + i * 16 + g) * STR + co;
            float r0 = As[idx];
            float r1 = As[idx + 8 * STR];
            float r2 = As[idx + 4];
            float r3 = As[idx + 8 * STR + 4];
            ah[i][0] = hi_part(r0); al[i][0] = r0 - ah[i][0];
            ah[i][1] = hi_part(r1); al[i][1] = r1 - ah[i][1];
            ah[i][2] = hi_part(r2); al[i][2] = r2 - ah[i][2];
            ah[i][3] = hi_part(r3); al[i][3] = r3 - ah[i][3];
        }
#pragma unroll
        for (int j = 0; j < 4; j++) {
            int bidx = (wn * 32 + j * 8 + g) * STR + co;
            float b0 = Bs[bidx];
            float b1 = Bs[bidx + 4];
            float bh0 = hi_part(b0), bl0 = b0 - bh0;
            float bh1 = hi_part(b1), bl1 = b1 - bh1;
#pragma unroll
            for (int i = 0; i < 4; i++) {
                mma_tf32(acc[i][j], ah[i][0], ah[i][1], ah[i][2], ah[i][3], bh0, bh1);
                mma_tf32(acc[i][j], al[i][0], al[i][1], al[i][2], al[i][3], bh0, bh1);
                mma_tf32(acc[i][j], ah[i][0], ah[i][1], ah[i][2], ah[i][3], bl0, bl1);
            }
        }
    }
}

// ---------------------------------------------------------------------------
// Kernel 0: transpose V -> g_Vt  [B][N][C] -> [B][C][N]
// ---------------------------------------------------------------------------
__global__ __launch_bounds__(256) void transpose_v_kernel(const float* __restrict__ V)
{
    __shared__ float t[32][33];
    const int b  = blockIdx.z;
    const int n0 = blockIdx.y * 32;
    const int c0 = blockIdx.x * 32;
    const float* Vb = V + (size_t)b * N_ * C_;
    float* Tb = g_Vt + (size_t)b * C_ * N_;
    const int x = threadIdx.x, y = threadIdx.y;
#pragma unroll
    for (int dy = 0; dy < 32; dy += 8)
        t[y + dy][x] = Vb[(size_t)(n0 + y + dy) * C_ + c0 + x];
    __syncthreads();
#pragma unroll
    for (int dy = 0; dy < 32; dy += 8)
        Tb[(size_t)(c0 + y + dy) * N_ + n0 + x] = t[x][y + dy];
}

// ---------------------------------------------------------------------------
// Kernel 1: attn = masked((Q K^T + dis) * 0.0625)
// ---------------------------------------------------------------------------
__global__ __launch_bounds__(256, 2) void qk_scores_kernel(
    const float* __restrict__ Q,
    const float* __restrict__ K,
    const float* __restrict__ dis,
    const int*   __restrict__ mask,
    float* __restrict__ attn)
{
    __shared__ float As[TILE];
    __shared__ float Bs[TILE];

    const int b     = blockIdx.z;
    const int qBase = blockIdx.y * 128;
    const int kBase = blockIdx.x * 128;

    const float* Qb = Q + (size_t)b * N_ * C_;
    const float* Kb = K + (size_t)b * N_ * C_;

    const int tid  = threadIdx.x;
    const int lane = tid & 31;
    const int w    = tid >> 5;
    const int wm   = w >> 2;
    const int wn   = w & 3;
    const int g    = lane >> 2;
    const int cq   = lane & 3;

    float acc[4][4][4];
#pragma unroll
    for (int i = 0; i < 4; i++)
#pragma unroll
        for (int j = 0; j < 4; j++)
#pragma unroll
            for (int r = 0; r < 4; r++) acc[i][j][r] = 0.0f;

    for (int c0 = 0; c0 < C_; c0 += KC) {
        load_tiles(Qb, Kb, C_, C_, qBase, kBase, c0, As, Bs, tid);
        __syncthreads();
        compute_chunk(As, Bs, acc, wm, wn, g, cq);
        __syncthreads();
    }

    // epilogue: add dis, scale, mask
#pragma unroll
    for (int i = 0; i < 4; i++) {
        int r0 = qBase + wm * 64 + i * 16 + g;
        int r1 = r0 + 8;
#pragma unroll
        for (int j = 0; j < 4; j++) {
            int col = kBase + wn * 32 + j * 8 + 2 * cq;
            size_t i0 = ((size_t)b * N_ + r0) * N_ + col;
            size_t i1 = ((size_t)b * N_ + r1) * N_ + col;
            float2 d0 = *reinterpret_cast<const float2*>(&dis[i0]);
            float2 d1 = *reinterpret_cast<const float2*>(&dis[i1]);
            int2   m0 = *reinterpret_cast<const int2*>(&mask[i0]);
            int2   m1 = *reinterpret_cast<const int2*>(&mask[i1]);
            float2 o0, o1;
            o0.x = m0.x ? -INFINITY : (acc[i][j][0] + d0.x) * 0.0625f;
            o0.y = m0.y ? -INFINITY : (acc[i][j][1] + d0.y) * 0.0625f;
            o1.x = m1.x ? -INFINITY : (acc[i][j][2] + d1.x) * 0.0625f;
            o1.y = m1.y ? -INFINITY : (acc[i][j][3] + d1.y) * 0.0625f;
            *reinterpret_cast<float2*>(&attn[i0]) = o0;
            *reinterpret_cast<float2*>(&attn[i1]) = o1;
        }
    }
}

// ---------------------------------------------------------------------------
// Kernel 2: row softmax (rows of 1024), shuffle-based, float4 I/O
// ---------------------------------------------------------------------------
__global__ __launch_bounds__(256) void softmax_kernel(float* __restrict__ attn)
{
    __shared__ float s1[8], s2[8];
    const size_t base = (size_t)blockIdx.x * N_;
    const int t = threadIdx.x;
    const int w = t >> 5, lane = t & 31;

    float4 v = *reinterpret_cast<const float4*>(&attn[base + t * 4]);

    float m = fmaxf(fmaxf(v.x, v.y), fmaxf(v.z, v.w));
#pragma unroll
    for (int o = 16; o; o >>= 1) m = fmaxf(m, __shfl_xor_sync(0xffffffffu, m, o));
    if (lane == 0) s1[w] = m;
    __syncthreads();
    float M = s1[0];
#pragma unroll
    for (int i = 1; i < 8; i++) M = fmaxf(M, s1[i]);

    float4 p;
    p.x = __expf(v.x - M); p.y = __expf(v.y - M);
    p.z = __expf(v.z - M); p.w = __expf(v.w - M);
    float s = (p.x + p.y) + (p.z + p.w);
#pragma unroll
    for (int o = 16; o; o >>= 1) s += __shfl_xor_sync(0xffffffffu, s, o);
    if (lane == 0) s2[w] = s;
    __syncthreads();
    float S = s2[0];
#pragma unroll
    for (int i = 1; i < 8; i++) S += s2[i];
    float inv = 1.0f / S;

    p.x *= inv; p.y *= inv; p.z *= inv; p.w *= inv;
    *reinterpret_cast<float4*>(&attn[base + t * 4]) = p;
}

// ---------------------------------------------------------------------------
// Kernel 3: p_val = p_attn @ V (B from g_Vt, K-major) — same structure as qk
// ---------------------------------------------------------------------------
__global__ __launch_bounds__(256, 2) void pv_kernel(
    const float* __restrict__ P,
    float* __restrict__ out)
{
    __shared__ float As[TILE];
    __shared__ float Bs[TILE];

    const int b     = blockIdx.z;
    const int qBase = blockIdx.y * 128;
    const int nBase = blockIdx.x * 128;

    const float* Pb = P + (size_t)b * N_ * N_;
    const float* Vt = g_Vt + (size_t)b * C_ * N_;

    const int tid  = threadIdx.x;
    const int lane = tid & 31;
    const int w    = tid >> 5;
    const int wm   = w >> 2;
    const int wn   = w & 3;
    const int g    = lane >> 2;
    const int cq   = lane & 3;

    float acc[4][4][4];
#pragma unroll
    for (int i = 0; i < 4; i++)
#pragma unroll
        for (int j = 0; j < 4; j++)
#pragma unroll
            for (int r = 0; r < 4; r++) acc[i][j][r] = 0.0f;

    for (int k0 = 0; k0 < N_; k0 += KC) {
        load_tiles(Pb, Vt, N_, N_, qBase, nBase, k0, As, Bs, tid);
        __syncthreads();
        compute_chunk(As, Bs, acc, wm, wn, g, cq);
        __syncthreads();
    }

#pragma unroll
    for (int i = 0; i < 4; i++) {
        int r0 = qBase + wm * 64 + i * 16 + g;
        int r1 = r0 + 8;
#pragma unroll
        for (int j = 0; j < 4; j++) {
            int col = nBase + wn * 32 + j * 8 + 2 * cq;
            size_t i0 = ((size_t)b * N_ + r0) * C_ + col;
            size_t i1 = ((size_t)b * N_ + r1) * C_ + col;
            *reinterpret_cast<float2*>(&out[i0]) = make_float2(acc[i][j][0], acc[i][j][1]);
            *reinterpret_cast<float2*>(&out[i1]) = make_float2(acc[i][j][2], acc[i][j][3]);
        }
    }
}

// ---------------------------------------------------------------------------
// Launch
// ---------------------------------------------------------------------------
extern "C" void kernel_launch(void* const* d_in, const int* in_sizes, int n_in,
                              void* d_out, int out_size)
{
    const float* Q    = (const float*)d_in[0];
    const float* K    = (const float*)d_in[1];
    const float* V    = (const float*)d_in[2];
    const int*   mask = (const int*)d_in[3];
    const float* dis  = (const float*)d_in[4];

    float* out    = (float*)d_out;
    float* p_val  = out;                          // [B, N, C]
    float* p_attn = out + (size_t)B_ * N_ * C_;   // [B, N, N]

    transpose_v_kernel<<<dim3(C_ / 32, N_ / 32, B_), dim3(32, 8)>>>(V);
    qk_scores_kernel<<<dim3(N_ / 128, N_ / 128, B_), 256>>>(Q, K, dis, mask, p_attn);
    softmax_kernel<<<B_ * N_, 256>>>(p_attn);
    pv_kernel<<<dim3(C_ / 128, N_ / 128, B_), 256>>>(p_attn, p_val);
}

// round 10
// speedup vs baseline: 1.6884x; 1.1156x over previous
#include <cuda_runtime.h>
#include <math.h>
#include <stdint.h>

#define B_ 16
#define N_ 1024
#define C_ 256

#define KC    32                  // k-chunk (floats)
#define STR   36                  // smem row stride (floats); 144B rows, 16B-aligned
#define TILE  (128 * STR)         // floats per raw tile (18432 B)
#define DYN_BYTES (4 * TILE * 4)  // 2 buffers x (A,B) = 73728 B

// V transposed to [B][C][N]
static __device__ float g_Vt[(size_t)B_ * C_ * N_];

// ---------------------------------------------------------------------------
// mma.sync m16n8k8 tf32, row.col, fp32 accumulate
// ---------------------------------------------------------------------------
__device__ __forceinline__ void mma_tf32(float* d,
                                         float a0, float a1, float a2, float a3,
                                         float b0, float b1) {
    asm volatile(
        "mma.sync.aligned.m16n8k8.row.col.f32.tf32.tf32.f32 "
        "{%0,%1,%2,%3}, {%4,%5,%6,%7}, {%8,%9}, {%0,%1,%2,%3};"
        : "+f"(d[0]), "+f"(d[1]), "+f"(d[2]), "+f"(d[3])
        : "r"(__float_as_uint(a0)), "r"(__float_as_uint(a1)),
          "r"(__float_as_uint(a2)), "r"(__float_as_uint(a3)),
          "r"(__float_as_uint(b0)), "r"(__float_as_uint(b1)));
}

__device__ __forceinline__ float hi_part(float x) {
    return __uint_as_float(__float_as_uint(x) & 0xFFFFE000u);
}

// ---------------------------------------------------------------------------
// cp.async 16B gmem -> smem
// ---------------------------------------------------------------------------
__device__ __forceinline__ void cp16(uint32_t saddr, const float* g) {
    asm volatile("cp.async.ca.shared.global [%0], [%1], 16;"
                 :: "r"(saddr), "l"(g) : "memory");
}

__device__ __forceinline__ void load_tiles_async(
    const float* __restrict__ Ag, const float* __restrict__ Bg,
    int lda, int ldb, int aBase, int bBase, int k0,
    uint32_t sA, uint32_t sB, int tid)
{
#pragma unroll
    for (int e = 0; e < 4; e++) {
        int lin = tid + e * 256;
        int row = lin >> 3;            // 0..127
        int c4  = (lin & 7) * 4;       // 0..28
        uint32_t off = (uint32_t)(row * STR + c4) * 4;
        cp16(sA + off, &Ag[(size_t)(aBase + row) * lda + k0 + c4]);
        cp16(sB + off, &Bg[(size_t)(bBase + row) * ldb + k0 + c4]);
    }
    asm volatile("cp.async.commit_group;" ::: "memory");
}

// ---------------------------------------------------------------------------
// one k-chunk (KC=32): raw tiles -> register split -> 3xTF32 mma
// 8 warps (2x4), warp tile 64x32, 4x4 m16n8 tiles
// ---------------------------------------------------------------------------
__device__ __forceinline__ void compute_chunk(
    const float* __restrict__ As, const float* __restrict__ Bs,
    float acc[4][4][4], int wm, int wn, int g, int cq)
{
#pragma unroll
    for (int s = 0; s < KC; s += 8) {
        const int co = s + cq;
        float ah[4][4], al[4][4];
#pragma unroll
        for (int i = 0; i < 4; i++) {
            int idx = (wm * 64 + i * 16 + g) * STR + co;
            float r0 = As[idx];
            float r1 = As[idx + 8 * STR];
            float r2 = As[idx + 4];
            float r3 = As[idx + 8 * STR + 4];
            ah[i][0] = hi_part(r0); al[i][0] = r0 - ah[i][0];
            ah[i][1] = hi_part(r1); al[i][1] = r1 - ah[i][1];
            ah[i][2] = hi_part(r2); al[i][2] = r2 - ah[i][2];
            ah[i][3] = hi_part(r3); al[i][3] = r3 - ah[i][3];
        }
#pragma unroll
        for (int j = 0; j < 4; j++) {
            int bidx = (wn * 32 + j * 8 + g) * STR + co;
            float b0 = Bs[bidx];
            float b1 = Bs[bidx + 4];
            float bh0 = hi_part(b0), bl0 = b0 - bh0;
            float bh1 = hi_part(b1), bl1 = b1 - bh1;
#pragma unroll
            for (int i = 0; i < 4; i++) {
                mma_tf32(acc[i][j], ah[i][0], ah[i][1], ah[i][2], ah[i][3], bh0, bh1);
                mma_tf32(acc[i][j], al[i][0], al[i][1], al[i][2], al[i][3], bh0, bh1);
                mma_tf32(acc[i][j], ah[i][0], ah[i][1], ah[i][2], ah[i][3], bl0, bl1);
            }
        }
    }
}

// ---------------------------------------------------------------------------
// double-buffered mainloop shared by qk / pv
// ---------------------------------------------------------------------------
__device__ __forceinline__ void gemm_mainloop(
    const float* __restrict__ Ag, const float* __restrict__ Bg,
    int lda, int ldb, int aBase, int bBase, int nChunks,
    float* __restrict__ smem, uint32_t sbase,
    float acc[4][4][4], int tid, int wm, int wn, int g, int cq)
{
    // buffers: [buf][A|B][TILE]
    load_tiles_async(Ag, Bg, lda, ldb, aBase, bBase, 0,
                     sbase, sbase + TILE * 4, tid);

    for (int c = 0; c < nChunks; c++) {
        const int cur = c & 1;
        if (c + 1 < nChunks) {
            const int nxt = cur ^ 1;
            load_tiles_async(Ag, Bg, lda, ldb, aBase, bBase, (c + 1) * KC,
                             sbase + (uint32_t)(nxt * 2 * TILE) * 4,
                             sbase + (uint32_t)((nxt * 2 + 1) * TILE) * 4, tid);
            asm volatile("cp.async.wait_group 1;" ::: "memory");
        } else {
            asm volatile("cp.async.wait_group 0;" ::: "memory");
        }
        __syncthreads();
        compute_chunk(smem + cur * 2 * TILE, smem + (cur * 2 + 1) * TILE,
                      acc, wm, wn, g, cq);
        __syncthreads();
    }
}

// ---------------------------------------------------------------------------
// Kernel 0: transpose V -> g_Vt  [B][N][C] -> [B][C][N]
// ---------------------------------------------------------------------------
__global__ __launch_bounds__(256) void transpose_v_kernel(const float* __restrict__ V)
{
    __shared__ float t[32][33];
    const int b  = blockIdx.z;
    const int n0 = blockIdx.y * 32;
    const int c0 = blockIdx.x * 32;
    const float* Vb = V + (size_t)b * N_ * C_;
    float* Tb = g_Vt + (size_t)b * C_ * N_;
    const int x = threadIdx.x, y = threadIdx.y;
#pragma unroll
    for (int dy = 0; dy < 32; dy += 8)
        t[y + dy][x] = Vb[(size_t)(n0 + y + dy) * C_ + c0 + x];
    __syncthreads();
#pragma unroll
    for (int dy = 0; dy < 32; dy += 8)
        Tb[(size_t)(c0 + y + dy) * N_ + n0 + x] = t[x][y + dy];
}

// ---------------------------------------------------------------------------
// Kernel 1: attn = masked((Q K^T + dis) * 0.0625)
// ---------------------------------------------------------------------------
__global__ __launch_bounds__(256, 2) void qk_scores_kernel(
    const float* __restrict__ Q,
    const float* __restrict__ K,
    const float* __restrict__ dis,
    const int*   __restrict__ mask,
    float* __restrict__ attn)
{
    extern __shared__ float smem[];
    const uint32_t sbase = (uint32_t)__cvta_generic_to_shared(smem);

    const int b     = blockIdx.z;
    const int qBase = blockIdx.y * 128;
    const int kBase = blockIdx.x * 128;

    const int tid  = threadIdx.x;
    const int lane = tid & 31;
    const int w    = tid >> 5;
    const int wm   = w >> 2;
    const int wn   = w & 3;
    const int g    = lane >> 2;
    const int cq   = lane & 3;

    float acc[4][4][4];
#pragma unroll
    for (int i = 0; i < 4; i++)
#pragma unroll
        for (int j = 0; j < 4; j++)
#pragma unroll
            for (int r = 0; r < 4; r++) acc[i][j][r] = 0.0f;

    gemm_mainloop(Q + (size_t)b * N_ * C_, K + (size_t)b * N_ * C_,
                  C_, C_, qBase, kBase, C_ / KC,
                  smem, sbase, acc, tid, wm, wn, g, cq);

    // epilogue: add dis, scale, mask
#pragma unroll
    for (int i = 0; i < 4; i++) {
        int r0 = qBase + wm * 64 + i * 16 + g;
        int r1 = r0 + 8;
#pragma unroll
        for (int j = 0; j < 4; j++) {
            int col = kBase + wn * 32 + j * 8 + 2 * cq;
            size_t i0 = ((size_t)b * N_ + r0) * N_ + col;
            size_t i1 = ((size_t)b * N_ + r1) * N_ + col;
            float2 d0 = *reinterpret_cast<const float2*>(&dis[i0]);
            float2 d1 = *reinterpret_cast<const float2*>(&dis[i1]);
            int2   m0 = *reinterpret_cast<const int2*>(&mask[i0]);
            int2   m1 = *reinterpret_cast<const int2*>(&mask[i1]);
            float2 o0, o1;
            o0.x = m0.x ? -INFINITY : (acc[i][j][0] + d0.x) * 0.0625f;
            o0.y = m0.y ? -INFINITY : (acc[i][j][1] + d0.y) * 0.0625f;
            o1.x = m1.x ? -INFINITY : (acc[i][j][2] + d1.x) * 0.0625f;
            o1.y = m1.y ? -INFINITY : (acc[i][j][3] + d1.y) * 0.0625f;
            *reinterpret_cast<float2*>(&attn[i0]) = o0;
            *reinterpret_cast<float2*>(&attn[i1]) = o1;
        }
    }
}

// ---------------------------------------------------------------------------
// Kernel 2: row softmax (rows of 1024), shuffle-based, float4 I/O
// ---------------------------------------------------------------------------
__global__ __launch_bounds__(256) void softmax_kernel(float* __restrict__ attn)
{
    __shared__ float s1[8], s2[8];
    const size_t base = (size_t)blockIdx.x * N_;
    const int t = threadIdx.x;
    const int w = t >> 5, lane = t & 31;

    float4 v = *reinterpret_cast<const float4*>(&attn[base + t * 4]);

    float m = fmaxf(fmaxf(v.x, v.y), fmaxf(v.z, v.w));
#pragma unroll
    for (int o = 16; o; o >>= 1) m = fmaxf(m, __shfl_xor_sync(0xffffffffu, m, o));
    if (lane == 0) s1[w] = m;
    __syncthreads();
    float M = s1[0];
#pragma unroll
    for (int i = 1; i < 8; i++) M = fmaxf(M, s1[i]);

    float4 p;
    p.x = __expf(v.x - M); p.y = __expf(v.y - M);
    p.z = __expf(v.z - M); p.w = __expf(v.w - M);
    float s = (p.x + p.y) + (p.z + p.w);
#pragma unroll
    for (int o = 16; o; o >>= 1) s += __shfl_xor_sync(0xffffffffu, s, o);
    if (lane == 0) s2[w] = s;
    __syncthreads();
    float S = s2[0];
#pragma unroll
    for (int i = 1; i < 8; i++) S += s2[i];
    float inv = 1.0f / S;

    p.x *= inv; p.y *= inv; p.z *= inv; p.w *= inv;
    *reinterpret_cast<float4*>(&attn[base + t * 4]) = p;
}

// ---------------------------------------------------------------------------
// Kernel 3: p_val = p_attn @ V (B from g_Vt, K-major)
// ---------------------------------------------------------------------------
__global__ __launch_bounds__(256, 2) void pv_kernel(
    const float* __restrict__ P,
    float* __restrict__ out)
{
    extern __shared__ float smem[];
    const uint32_t sbase = (uint32_t)__cvta_generic_to_shared(smem);

    const int b     = blockIdx.z;
    const int qBase = blockIdx.y * 128;
    const int nBase = blockIdx.x * 128;

    const int tid  = threadIdx.x;
    const int lane = tid & 31;
    const int w    = tid >> 5;
    const int wm   = w >> 2;
    const int wn   = w & 3;
    const int g    = lane >> 2;
    const int cq   = lane & 3;

    float acc[4][4][4];
#pragma unroll
    for (int i = 0; i < 4; i++)
#pragma unroll
        for (int j = 0; j < 4; j++)
#pragma unroll
            for (int r = 0; r < 4; r++) acc[i][j][r] = 0.0f;

    gemm_mainloop(P + (size_t)b * N_ * N_, g_Vt + (size_t)b * C_ * N_,
                  N_, N_, qBase, nBase, N_ / KC,
                  smem, sbase, acc, tid, wm, wn, g, cq);

#pragma unroll
    for (int i = 0; i < 4; i++) {
        int r0 = qBase + wm * 64 + i * 16 + g;
        int r1 = r0 + 8;
#pragma unroll
        for (int j = 0; j < 4; j++) {
            int col = nBase + wn * 32 + j * 8 + 2 * cq;
            size_t i0 = ((size_t)b * N_ + r0) * C_ + col;
            size_t i1 = ((size_t)b * N_ + r1) * C_ + col;
            *reinterpret_cast<float2*>(&out[i0]) = make_float2(acc[i][j][0], acc[i][j][1]);
            *reinterpret_cast<float2*>(&out[i1]) = make_float2(acc[i][j][2], acc[i][j][3]);
        }
    }
}

// ---------------------------------------------------------------------------
// Launch
// ---------------------------------------------------------------------------
extern "C" void kernel_launch(void* const* d_in, const int* in_sizes, int n_in,
                              void* d_out, int out_size)
{
    const float* Q    = (const float*)d_in[0];
    const float* K    = (const float*)d_in[1];
    const float* V    = (const float*)d_in[2];
    const int*   mask = (const int*)d_in[3];
    const float* dis  = (const float*)d_in[4];

    float* out    = (float*)d_out;
    float* p_val  = out;                          // [B, N, C]
    float* p_attn = out + (size_t)B_ * N_ * C_;   // [B, N, N]

    cudaFuncSetAttribute(qk_scores_kernel,
                         cudaFuncAttributeMaxDynamicSharedMemorySize, DYN_BYTES);
    cudaFuncSetAttribute(pv_kernel,
                         cudaFuncAttributeMaxDynamicSharedMemorySize, DYN_BYTES);

    transpose_v_kernel<<<dim3(C_ / 32, N_ / 32, B_), dim3(32, 8)>>>(V);
    qk_scores_kernel<<<dim3(N_ / 128, N_ / 128, B_), 256, DYN_BYTES>>>(Q, K, dis, mask, p_attn);
    softmax_kernel<<<B_ * N_, 256>>>(p_attn);
    pv_kernel<<<dim3(C_ / 128, N_ / 128, B_), 256, DYN_BYTES>>>(p_attn, p_val);
}